// round 9
// baseline (speedup 1.0000x reference)
#include <cuda_runtime.h>
#include <cstdint>

#define S 7
#define NB 49            // S*S cells / boxes per image
#define BATCH 4096
#define NCLS 20
#define DEPTH 30         // B*5 + C
#define NTH 64

#define TOTAL_E (BATCH * NB)      // 200704
#define G 128                     // AP blocks (4096/32 images)
#define EPB 1568                  // entries per AP block (32 images * 49)
#define NSEG 49                   // 32-entry segments per AP block

// Scratch (device globals; zero-init at load; last k_apfinal block re-zeroes)
__device__ unsigned short g_entries[TOTAL_E];
__device__ int   g_tp_part[NCLS][G];   // raw per-AP-block counts
__device__ int   g_fp_part[NCLS][G];
__device__ float g_ap_blk[G];
__device__ int   g_gt[NCLS];
__device__ int   g_done;

__device__ __forceinline__ float sigm(float x) {
    return 1.0f / (1.0f + expf(-x));
}

__device__ __forceinline__ float iou4(float4 a, float4 b) {
    float lx = fmaxf(a.x, b.x), ly = fmaxf(a.y, b.y);
    float rx = fminf(a.z, b.z), ry = fminf(a.w, b.w);
    float w = fmaxf(rx - lx, 0.0f), h = fmaxf(ry - ly, 0.0f);
    float inter = w * h;
    float aa = (a.z - a.x) * (a.w - a.y);
    float ab = (b.z - b.x) * (b.w - b.y);
    return inter / (aa + ab - inter);
}

// Working arrays overlaid on the staging buffer (reads of sbuf all complete
// before any overlay write).
struct __align__(16) Work {
    float4 sbox[NB];                 // sorted boxes
    float4 ubox[NB];                 // unsorted boxes
    unsigned long long supm[NB];     // suppression masks (rank space)
    unsigned long long skeys[NB];    // sort keys (cell space)
    int      ucls[NB];               // unsorted class
    int      scls[NB];               // sorted class | confflag<<5
    unsigned candw[NB];              // best<<2 | confflag<<1 | iouflag
};

// ---------------------------------------------------------------------------
// Kernel 1: decode, sort, NMS, GT matching + direct global count atomics.
// One image per block, 64 threads.
// ---------------------------------------------------------------------------
__global__ __launch_bounds__(NTH) void k_per_image(const float* __restrict__ target,
                                                   const float* __restrict__ output) {
    int img = blockIdx.x;
    int t = threadIdx.x;

    __shared__ __align__(16) float sbuf[NB * DEPTH];   // 5880 B, overlaid by Work
    __shared__ __align__(16) float4 gbx[NB];           // GT boxes (separate)
    __shared__ int gcl[NB];
    __shared__ unsigned char gvl[NB];
    __shared__ unsigned long long gmask[NCLS];
    __shared__ unsigned long long pmask[NCLS];
    __shared__ unsigned long long keepm_s, tpm_s;

    if (t < NCLS) { gmask[t] = 0ULL; pmask[t] = 0ULL; }

    // ---- stage pred tensor (735 coalesced float2) ----
    {
        const float2* src = (const float2*)(output + (size_t)img * (NB * DEPTH));
        float2* dst = (float2*)sbuf;
        #pragma unroll 4
        for (int k = t; k < NB * DEPTH / 2; k += NTH) dst[k] = src[k];
    }
    __syncthreads();

    // ---- decode preds into registers (float2 smem reads) ----
    float4 p_box = make_float4(0.f, 0.f, 0.f, 0.f);
    unsigned long long p_key = 0;
    int p_cls = 0;
    int iy = t / S, jx = t - iy * S;
    if (t < NB) {
        const float2* r2 = (const float2*)sbuf + t * 15;
        float2 f01 = r2[0], f23 = r2[1], f45 = r2[2], f67 = r2[3], f89 = r2[4];
        float c0 = f45.x, c1 = f89.y;
        bool resp = c1 > c0;
        float craw = resp ? c1 : c0;
        float x = sigm(resp ? f45.y : f01.x);
        float y = sigm(resp ? f67.x : f01.y);
        float w = sigm(resp ? f67.y : f23.x);
        float h = sigm(resp ? f89.x : f23.y);
        float cx = (x + (float)jx) * 64.0f;
        float cy = (y + (float)iy) * 64.0f;
        float W = w * 448.0f, H = h * 448.0f;
        p_box = make_float4(cx - 0.5f * W, cy - 0.5f * H, cx + 0.5f * W, cy + 0.5f * H);
        float conf = sigm(craw);
        // key: conf float bits (positive floats -> monotone as uint) | index tiebreak
        p_key = ((unsigned long long)__float_as_uint(conf) << 6) | (unsigned)(63 - t);
        // class argmax (first-max on ties), float2 pairs
        float2 p = r2[5];
        float bv = p.x; int ci = 0;
        if (p.y > bv) { bv = p.y; ci = 1; }
        #pragma unroll
        for (int k = 1; k < 10; k++) {
            p = r2[5 + k];
            if (p.x > bv) { bv = p.x; ci = 2 * k; }
            if (p.y > bv) { bv = p.y; ci = 2 * k + 1; }
        }
        p_cls = ci;
    }
    __syncthreads();   // all pred-stage reads done

    // ---- stage GT tensor over same buffer ----
    {
        const float2* src = (const float2*)(target + (size_t)img * (NB * DEPTH));
        float2* dst = (float2*)sbuf;
        #pragma unroll 4
        for (int k = t; k < NB * DEPTH / 2; k += NTH) dst[k] = src[k];
    }
    __syncthreads();

    // ---- decode GT directly into separate smem arrays ----
    if (t < NB) {
        const float2* r2 = (const float2*)sbuf + t * 15;
        float2 f01 = r2[0], f23 = r2[1], f45 = r2[2];
        int gval = (f45.x > 0.5f) ? 1 : 0;
        float cx = (f01.x + (float)jx) * 64.0f;
        float cy = (f01.y + (float)iy) * 64.0f;
        float W = f23.x * 448.0f, H = f23.y * 448.0f;
        gbx[t] = make_float4(cx - 0.5f * W, cy - 0.5f * H, cx + 0.5f * W, cy + 0.5f * H);
        float2 p = r2[5];
        float bv = p.x; int ci = 0;
        if (p.y > bv) { bv = p.y; ci = 1; }
        #pragma unroll
        for (int k = 1; k < 10; k++) {
            p = r2[5 + k];
            if (p.x > bv) { bv = p.x; ci = 2 * k; }
            if (p.y > bv) { bv = p.y; ci = 2 * k + 1; }
        }
        gcl[t] = ci;
        gvl[t] = (unsigned char)gval;
        if (gval) {
            atomicOr(&gmask[ci], 1ULL << t);
            atomicAdd(&g_gt[ci], 1);
        }
    }
    __syncthreads();   // all GT-stage reads done -> safe to overlay

    Work* Wk = (Work*)sbuf;
    if (t < NB) {
        Wk->ubox[t] = p_box;
        Wk->ucls[t] = p_cls;
        Wk->skeys[t] = p_key;
    }
    __syncthreads();

    // ---- stable descending rank-sort on packed keys + per-class pred masks ----
    if (t < NB) {
        unsigned long long ki = Wk->skeys[t];
        int rank = 0;
        #pragma unroll 7
        for (int j = 0; j < NB; j++) rank += (Wk->skeys[j] > ki);
        Wk->sbox[rank] = Wk->ubox[t];
        int cf = ((unsigned)(ki >> 6) > 0x3F000000u) ? 1 : 0;   // conf > 0.5 exact
        Wk->scls[rank] = Wk->ucls[t] | (cf << 5);
        atomicOr(&pmask[Wk->ucls[t]], 1ULL << rank);
    }
    __syncthreads();

    // ---- suppression masks + best-GT via class bitmasks; pack cand word ----
    if (t < NB) {
        float4 a = Wk->sbox[t];
        int sv = Wk->scls[t];
        int ci = sv & 31;

        unsigned long long m = 0;
        unsigned long long cand = pmask[ci] & (~0ULL << (t + 1));   // t<=48
        while (cand) {
            int j = __ffsll((long long)cand) - 1;
            cand &= cand - 1;
            if (iou4(a, Wk->sbox[j]) > 0.5f) m |= (1ULL << j);
        }
        Wk->supm[t] = m;

        float mxv = -1.0f;
        int bj = 0;
        unsigned long long gm = gmask[ci];
        while (gm) {
            int j = __ffsll((long long)gm) - 1;
            gm &= gm - 1;
            float v = iou4(a, gbx[j]);
            if (v > mxv) { mxv = v; bj = j; }
        }
        Wk->candw[t] = ((unsigned)bj << 2) | (unsigned)(((sv >> 5) & 1) << 1)
                     | (unsigned)(mxv > 0.5f);
    }
    __syncthreads();

    // ---- fused sequential NMS + greedy matching (thread 0, one pass) ----
    if (t == 0) {
        unsigned long long suppressed = 0, matched = 0, tpm = 0, keepm = 0;
        for (int i = 0; i < NB; i++) {
            unsigned long long sm = Wk->supm[i];
            unsigned cw = Wk->candw[i];
            bool keep = !((suppressed >> i) & 1ULL);
            if (keep) { suppressed |= sm; keepm |= (1ULL << i); }
            int b = (int)(cw >> 2);
            bool hit = keep && ((cw & 3u) == 3u) && !((matched >> b) & 1ULL);
            if (hit) { matched |= (1ULL << b); tpm |= (1ULL << i); }
        }
        keepm_s = keepm;
        tpm_s = tpm;
    }
    __syncthreads();

    // ---- emit packed entry + direct global count atomics ----
    if (t < NB) {
        unsigned cw = Wk->candw[t];
        int sc = Wk->scls[t] & 31;
        bool vp = (((keepm_s >> t) & 1ULL) != 0ULL) && ((cw & 2u) != 0u);
        bool tp = ((tpm_s >> t) & 1ULL) != 0ULL;
        unsigned v = (unsigned)sc
                   | (vp ? 32u : 0u)
                   | (tp ? 64u : 0u)
                   | (gvl[t] ? 128u : 0u)
                   | ((unsigned)gcl[t] << 8);
        g_entries[img * NB + t] = (unsigned short)v;
        if (vp) {
            int b = img >> 5;
            if (tp) atomicAdd(&g_tp_part[sc][b], 1);
            else    atomicAdd(&g_fp_part[sc][b], 1);
        }
    }
}

// ---------------------------------------------------------------------------
// Kernel 2: per-block AP contributions (hierarchical prefix) + fused final
// reduction by the last-arriving block (done-counter pattern).
// ---------------------------------------------------------------------------
__global__ __launch_bounds__(256) void k_apfinal(float* __restrict__ out) {
    int b = blockIdx.x, t = threadIdx.x;
    int lane = t & 31, w = t >> 5;

    __shared__ unsigned short se[EPB];        // 3136 B
    __shared__ int s_tpc[NSEG][NCLS];
    __shared__ int s_fpc[NSEG][NCLS];
    __shared__ int s_base[2][NCLS];           // [0]=tp base, [1]=fp base
    __shared__ float s_wsum[8];
    __shared__ int s_last;
    __shared__ float sv[G];

    // stage entries (196 uint4 loads, coalesced)
    {
        const uint4* src = (const uint4*)(g_entries + b * EPB);
        uint4* d4 = (uint4*)se;
        if (t < EPB * 2 / 16) d4[t] = src[t];
    }
    // zero segment counters
    {
        int* z0 = &s_tpc[0][0];
        int* z1 = &s_fpc[0][0];
        for (int k = t; k < NSEG * NCLS; k += 256) { z0[k] = 0; z1[k] = 0; }
    }
    // exclusive block-prefix bases: 40 (class, tp|fp) pairs over 8 warps
    #pragma unroll
    for (int r = 0; r < 5; r++) {
        int pair = w * 5 + r;                 // 0..39
        int c = pair % NCLS;
        int which = pair / NCLS;
        const int* col = which ? g_fp_part[c] : g_tp_part[c];
        int sum = 0;
        #pragma unroll
        for (int ch = 0; ch < G / 32; ch++) {
            int idx = ch * 32 + lane;
            if (idx < b) sum += col[idx];
        }
        #pragma unroll
        for (int o = 16; o > 0; o >>= 1)
            sum += __shfl_xor_sync(0xffffffffu, sum, o);
        if (lane == 0) s_base[which][c] = sum;
    }
    __syncthreads();

    // Phase A: per-segment per-class counts
    for (int e = t; e < EPB; e += 256) {
        unsigned v = se[e];
        if (v & 32u) {
            int s = e >> 5;
            int c = v & 31u;
            if (v & 64u) atomicAdd(&s_tpc[s][c], 1);
            else         atomicAdd(&s_fpc[s][c], 1);
        }
    }
    __syncthreads();

    // Phase B: exclusive scan over 49 segments per (class, tp|fp)
    if (t < NCLS * 2) {
        int c = t % NCLS;
        int* col0 = (t < NCLS) ? &s_tpc[0][c] : &s_fpc[0][c];
        int acc = 0;
        #pragma unroll
        for (int s = 0; s < NSEG; s++) {
            int* p = col0 + s * NCLS;
            int x = *p;
            *p = acc;
            acc += x;
        }
    }
    __syncthreads();

    // Phase C: within-segment prefix via match_any/ballot, sum TP contributions
    float acc = 0.0f;
    for (int s = w; s < NSEG; s += 8) {
        unsigned v = se[s * 32 + lane];
        bool valid = (v & 32u) != 0;
        int c = v & 31u;
        bool tp = (v & 64u) != 0;
        unsigned cc = valid ? (unsigned)c : 255u;
        unsigned peers = __match_any_sync(0xffffffffu, cc);
        unsigned tpb = __ballot_sync(0xffffffffu, tp);
        if (tp) {
            unsigned ltm = (1u << lane) - 1u;
            int Tw = __popc(peers & tpb & ltm);
            int Fw = __popc(peers & ltm) - Tw;
            int T = s_base[0][c] + s_tpc[s][c] + Tw;
            int F = s_base[1][c] + s_fpc[s][c] + Fw;
            float denr = (float)g_gt[c] + 1e-6f;
            bool first = (b == 0) && (s == 0) && (lane == 0);
            float p_prev = first ? 1.0f
                                 : (float)T / ((float)(T + F) + 1e-6f);
            float p_new = (float)(T + 1) / ((float)(T + 1 + F) + 1e-6f);
            acc += (1.0f / denr) * 0.5f * (p_prev + p_new);
        }
    }

    #pragma unroll
    for (int o = 16; o > 0; o >>= 1)
        acc += __shfl_xor_sync(0xffffffffu, acc, o);
    if (lane == 0) s_wsum[w] = acc;
    __syncthreads();
    if (t == 0) {
        float s = 0.0f;
        #pragma unroll
        for (int i = 0; i < 8; i++) s += s_wsum[i];
        g_ap_blk[b] = s;
        __threadfence();
        int r = atomicAdd(&g_done, 1);
        s_last = (r == G - 1) ? 1 : 0;
    }
    __syncthreads();

    // Last block: final reduction, output, re-zero accumulators for next replay.
    if (s_last) {
        __threadfence();   // acquire: see all blocks' g_ap_blk stores
        if (t < G) sv[t] = g_ap_blk[t];
        __syncthreads();
        #pragma unroll
        for (int o = 64; o > 0; o >>= 1) {
            if (t < o && t + o < G) sv[t] += sv[t + o];
            __syncthreads();
        }
        if (t == 0) {
            int n = 0;
            #pragma unroll
            for (int c = 0; c < NCLS; c++) n += (g_gt[c] > 0);
            out[0] = sv[0] / fmaxf((float)n, 1.0f);
            g_done = 0;
        }
        __syncthreads();   // t==0 done reading g_gt
        int* tp0 = &g_tp_part[0][0];
        int* fp0 = &g_fp_part[0][0];
        for (int k = t; k < NCLS * G; k += 256) { tp0[k] = 0; fp0[k] = 0; }
        if (t < NCLS) g_gt[t] = 0;
    }
}

extern "C" void kernel_launch(void* const* d_in, const int* in_sizes, int n_in,
                              void* d_out, int out_size) {
    const float* target = (const float*)d_in[0];
    const float* output = (const float*)d_in[1];
    float* out = (float*)d_out;

    k_per_image<<<BATCH, NTH>>>(target, output);
    k_apfinal<<<G, 256>>>(out);
}

// round 11
// speedup vs baseline: 1.2088x; 1.2088x over previous
#include <cuda_runtime.h>
#include <cstdint>

#define S 7
#define NB 49            // S*S cells / boxes per image
#define BATCH 4096
#define NCLS 20
#define DEPTH 30         // B*5 + C
#define NWARP 4          // images per block (one warp each)
#define NTH (NWARP * 32)
#define NBLK (BATCH / NWARP)   // 1024

#define TOTAL_E (BATCH * NB)      // 200704
#define G 128                     // AP blocks (4096/32 images)
#define EPB 1568                  // entries per AP block (32 images * 49)
#define NSEG 49                   // 32-entry segments per AP block
#define FULLM 0xffffffffu

// Scratch (device globals; zero-init at load; k_final re-zeroes accumulators)
__device__ unsigned short g_entries[TOTAL_E];
__device__ int   g_tp_part[NCLS][G];   // raw per-AP-block counts
__device__ int   g_fp_part[NCLS][G];
__device__ float g_ap_blk[G];
__device__ int   g_gt[NCLS];

__device__ __forceinline__ float sigm(float x) {
    return 1.0f / (1.0f + expf(-x));
}

__device__ __forceinline__ float iou4(float4 a, float4 b) {
    float lx = fmaxf(a.x, b.x), ly = fmaxf(a.y, b.y);
    float rx = fminf(a.z, b.z), ry = fminf(a.w, b.w);
    float w = fmaxf(rx - lx, 0.0f), h = fmaxf(ry - ly, 0.0f);
    float inter = w * h;
    float aa = (a.z - a.x) * (a.w - a.y);
    float ab = (b.z - b.x) * (b.w - b.y);
    return inter / (aa + ab - inter);
}

// Working arrays overlaid on the staging buffer (all sbuf reads complete
// before any overlay write; enforced by __syncwarp).
struct __align__(16) Work {
    float4 sbox[NB];                 // sorted boxes
    float4 ubox[NB];                 // unsorted boxes
    unsigned long long supm[NB];     // suppression masks (rank space)
    unsigned long long skeys[NB];    // sort keys (cell space)
    int      ucls[NB];               // unsorted class
    int      scls[NB];               // sorted class | confflag<<5
    unsigned candw[NB];              // best<<2 | confflag<<1 | iouflag
};

struct __align__(16) PerImg {
    float sbuf[1472];                // 5888 B staging; Work (2940 B) overlays
    float4 gbx[NB];
    int   gcl[NB];
    unsigned char gvl[52];
    unsigned long long gmask[NCLS];
    unsigned long long pmask[NCLS];
    unsigned long long keepm, tpm;
};

// ---------------------------------------------------------------------------
// Kernel 1: warp-per-image decode, sort, NMS, GT matching. No block barriers.
// ---------------------------------------------------------------------------
__global__ __launch_bounds__(NTH) void k_per_image(const float* __restrict__ target,
                                                   const float* __restrict__ output) {
    __shared__ PerImg sm[NWARP];
    int w = threadIdx.x >> 5;
    int lane = threadIdx.x & 31;
    int img = blockIdx.x * NWARP + w;
    PerImg* P = &sm[w];
    Work* Wk = (Work*)P->sbuf;

    if (lane < NCLS) { P->gmask[lane] = 0ULL; P->pmask[lane] = 0ULL; }

    // ---- stage pred tensor (735 float2, coalesced within warp) ----
    {
        const float2* src = (const float2*)(output + (size_t)img * (NB * DEPTH));
        float2* dst = (float2*)P->sbuf;
        #pragma unroll
        for (int k = lane; k < NB * DEPTH / 2; k += 32) dst[k] = src[k];
    }
    __syncwarp();

    // ---- decode preds into registers (2 boxes per lane) ----
    float4 pbox[2];
    unsigned long long pkey[2];
    int pcls[2];
    #pragma unroll
    for (int r = 0; r < 2; r++) {
        int t = lane + 32 * r;
        pkey[r] = 0; pcls[r] = 0;
        pbox[r] = make_float4(0.f, 0.f, 0.f, 0.f);
        if (t < NB) {
            const float2* r2 = (const float2*)P->sbuf + t * 15;
            float2 f01 = r2[0], f23 = r2[1], f45 = r2[2], f67 = r2[3], f89 = r2[4];
            float c0 = f45.x, c1 = f89.y;
            bool resp = c1 > c0;
            float craw = resp ? c1 : c0;
            float x = sigm(resp ? f45.y : f01.x);
            float y = sigm(resp ? f67.x : f01.y);
            float wd = sigm(resp ? f67.y : f23.x);
            float ht = sigm(resp ? f89.x : f23.y);
            int iy = t / S, jx = t - iy * S;
            float cx = (x + (float)jx) * 64.0f;
            float cy = (y + (float)iy) * 64.0f;
            float W = wd * 448.0f, H = ht * 448.0f;
            pbox[r] = make_float4(cx - 0.5f * W, cy - 0.5f * H, cx + 0.5f * W, cy + 0.5f * H);
            float conf = sigm(craw);
            pkey[r] = ((unsigned long long)__float_as_uint(conf) << 6) | (unsigned)(63 - t);
            float2 p = r2[5];
            float bv = p.x; int ci = 0;
            if (p.y > bv) { bv = p.y; ci = 1; }
            #pragma unroll
            for (int k = 1; k < 10; k++) {
                p = r2[5 + k];
                if (p.x > bv) { bv = p.x; ci = 2 * k; }
                if (p.y > bv) { bv = p.y; ci = 2 * k + 1; }
            }
            pcls[r] = ci;
        }
    }
    __syncwarp();   // all pred-stage reads done

    // ---- stage GT tensor over same buffer ----
    {
        const float2* src = (const float2*)(target + (size_t)img * (NB * DEPTH));
        float2* dst = (float2*)P->sbuf;
        #pragma unroll
        for (int k = lane; k < NB * DEPTH / 2; k += 32) dst[k] = src[k];
    }
    __syncwarp();

    // ---- decode GT into separate smem arrays + warp-aggregated GT counts ----
    #pragma unroll
    for (int r = 0; r < 2; r++) {
        int t = lane + 32 * r;
        int gval = 0, ci = 255;
        if (t < NB) {
            const float2* r2 = (const float2*)P->sbuf + t * 15;
            float2 f01 = r2[0], f23 = r2[1], f45 = r2[2];
            gval = (f45.x > 0.5f) ? 1 : 0;
            int iy = t / S, jx = t - iy * S;
            float cx = (f01.x + (float)jx) * 64.0f;
            float cy = (f01.y + (float)iy) * 64.0f;
            float W = f23.x * 448.0f, H = f23.y * 448.0f;
            P->gbx[t] = make_float4(cx - 0.5f * W, cy - 0.5f * H, cx + 0.5f * W, cy + 0.5f * H);
            float2 p = r2[5];
            float bv = p.x; ci = 0;
            if (p.y > bv) { bv = p.y; ci = 1; }
            #pragma unroll
            for (int k = 1; k < 10; k++) {
                p = r2[5 + k];
                if (p.x > bv) { bv = p.x; ci = 2 * k; }
                if (p.y > bv) { bv = p.y; ci = 2 * k + 1; }
            }
            P->gcl[t] = ci;
            P->gvl[t] = (unsigned char)gval;
            if (gval) atomicOr(&P->gmask[ci], 1ULL << t);
        }
        // warp-aggregated g_gt atomics (sentinel 255 for non-GT lanes)
        unsigned key = gval ? (unsigned)ci : 255u;
        unsigned peers = __match_any_sync(FULLM, key);
        if (gval) {
            int ldr = __ffs(peers) - 1;
            if (lane == ldr) atomicAdd(&g_gt[ci], __popc(peers));
        }
    }
    __syncwarp();   // all GT-stage reads done -> safe to overlay

    #pragma unroll
    for (int r = 0; r < 2; r++) {
        int t = lane + 32 * r;
        if (t < NB) {
            Wk->ubox[t] = pbox[r];
            Wk->ucls[t] = pcls[r];
            Wk->skeys[t] = pkey[r];
        }
    }
    __syncwarp();

    // ---- stable descending rank-sort + per-class pred masks ----
    #pragma unroll
    for (int r = 0; r < 2; r++) {
        int t = lane + 32 * r;
        if (t < NB) {
            unsigned long long ki = Wk->skeys[t];
            int rank = 0;
            #pragma unroll 7
            for (int j = 0; j < NB; j++) rank += (Wk->skeys[j] > ki);  // broadcast LDS
            Wk->sbox[rank] = Wk->ubox[t];
            int cf = ((unsigned)(ki >> 6) > 0x3F000000u) ? 1 : 0;   // conf > 0.5 exact
            Wk->scls[rank] = Wk->ucls[t] | (cf << 5);
            atomicOr(&P->pmask[Wk->ucls[t]], 1ULL << rank);
        }
    }
    __syncwarp();

    // ---- suppression masks + best-GT via class bitmasks ----
    #pragma unroll
    for (int r = 0; r < 2; r++) {
        int t = lane + 32 * r;
        if (t < NB) {
            float4 a = Wk->sbox[t];
            int sv = Wk->scls[t];
            int ci = sv & 31;

            unsigned long long m = 0;
            unsigned long long cand = P->pmask[ci] & (~0ULL << (t + 1));   // t<=48
            while (cand) {
                int j = __ffsll((long long)cand) - 1;
                cand &= cand - 1;
                if (iou4(a, Wk->sbox[j]) > 0.5f) m |= (1ULL << j);
            }
            Wk->supm[t] = m;

            float mxv = -1.0f;
            int bj = 0;
            unsigned long long gm = P->gmask[ci];
            while (gm) {
                int j = __ffsll((long long)gm) - 1;
                gm &= gm - 1;
                float v = iou4(a, P->gbx[j]);
                if (v > mxv) { mxv = v; bj = j; }
            }
            Wk->candw[t] = ((unsigned)bj << 2) | (unsigned)(((sv >> 5) & 1) << 1)
                         | (unsigned)(mxv > 0.5f);
        }
    }
    __syncwarp();

    // ---- fused sequential NMS + greedy matching (lane 0, one pass) ----
    if (lane == 0) {
        unsigned long long suppressed = 0, matched = 0, tpm = 0, keepm = 0;
        for (int i = 0; i < NB; i++) {
            unsigned long long smk = Wk->supm[i];
            unsigned cw = Wk->candw[i];
            bool keep = !((suppressed >> i) & 1ULL);
            if (keep) { suppressed |= smk; keepm |= (1ULL << i); }
            int b = (int)(cw >> 2);
            bool hit = keep && ((cw & 3u) == 3u) && !((matched >> b) & 1ULL);
            if (hit) { matched |= (1ULL << b); tpm |= (1ULL << i); }
        }
        P->keepm = keepm;
        P->tpm = tpm;
    }
    __syncwarp();

    // ---- emit packed entries + warp-aggregated TP/FP count atomics ----
    unsigned long long keepm = P->keepm, tpm = P->tpm;
    int apb = img >> 5;
    #pragma unroll
    for (int r = 0; r < 2; r++) {
        int t = lane + 32 * r;
        bool vp = false, tp = false;
        int sc = 0;
        if (t < NB) {
            unsigned cw = Wk->candw[t];
            sc = Wk->scls[t] & 31;
            vp = (((keepm >> t) & 1ULL) != 0ULL) && ((cw & 2u) != 0u);
            tp = ((tpm >> t) & 1ULL) != 0ULL;
            unsigned v = (unsigned)sc
                       | (vp ? 32u : 0u)
                       | (tp ? 64u : 0u)
                       | (P->gvl[t] ? 128u : 0u)
                       | ((unsigned)P->gcl[t] << 8);
            g_entries[img * NB + t] = (unsigned short)v;
        }
        // aggregate on (class, tp) among valid preds; sentinel for others
        unsigned key = vp ? ((unsigned)sc | (tp ? 256u : 0u)) : 1023u;
        unsigned peers = __match_any_sync(FULLM, key);
        if (vp) {
            int ldr = __ffs(peers) - 1;
            if (lane == ldr) {
                int n = __popc(peers);
                if (tp) atomicAdd(&g_tp_part[sc][apb], n);
                else    atomicAdd(&g_fp_part[sc][apb], n);
            }
        }
    }
}

// ---------------------------------------------------------------------------
// Kernel 2: per-block AP contributions (hierarchical prefix), R7-proven.
// ---------------------------------------------------------------------------
__global__ __launch_bounds__(256) void k_apfinal() {
    int b = blockIdx.x, t = threadIdx.x;
    int lane = t & 31, w = t >> 5;

    __shared__ unsigned short se[EPB];        // 3136 B
    __shared__ int s_tpc[NSEG][NCLS];
    __shared__ int s_fpc[NSEG][NCLS];
    __shared__ int s_base[2][NCLS];           // [0]=tp base, [1]=fp base
    __shared__ float s_wsum[8];

    // stage entries (196 uint4 loads, coalesced)
    {
        const uint4* src = (const uint4*)(g_entries + b * EPB);
        uint4* d4 = (uint4*)se;
        if (t < EPB * 2 / 16) d4[t] = src[t];
    }
    // zero segment counters
    {
        int* z0 = &s_tpc[0][0];
        int* z1 = &s_fpc[0][0];
        for (int k = t; k < NSEG * NCLS; k += 256) { z0[k] = 0; z1[k] = 0; }
    }
    // exclusive block-prefix bases: 40 (class, tp|fp) pairs over 8 warps
    #pragma unroll
    for (int r = 0; r < 5; r++) {
        int pair = w * 5 + r;                 // 0..39
        int c = pair % NCLS;
        int which = pair / NCLS;
        const int* col = which ? g_fp_part[c] : g_tp_part[c];
        int sum = 0;
        #pragma unroll
        for (int ch = 0; ch < G / 32; ch++) {
            int idx = ch * 32 + lane;
            if (idx < b) sum += col[idx];
        }
        #pragma unroll
        for (int o = 16; o > 0; o >>= 1)
            sum += __shfl_xor_sync(0xffffffffu, sum, o);
        if (lane == 0) s_base[which][c] = sum;
    }
    __syncthreads();

    // Phase A: per-segment per-class counts
    for (int e = t; e < EPB; e += 256) {
        unsigned v = se[e];
        if (v & 32u) {
            int s = e >> 5;
            int c = v & 31u;
            if (v & 64u) atomicAdd(&s_tpc[s][c], 1);
            else         atomicAdd(&s_fpc[s][c], 1);
        }
    }
    __syncthreads();

    // Phase B: exclusive scan over 49 segments per (class, tp|fp)
    if (t < NCLS * 2) {
        int c = t % NCLS;
        int* col0 = (t < NCLS) ? &s_tpc[0][c] : &s_fpc[0][c];
        int acc = 0;
        #pragma unroll
        for (int s = 0; s < NSEG; s++) {
            int* p = col0 + s * NCLS;
            int x = *p;
            *p = acc;
            acc += x;
        }
    }
    __syncthreads();

    // Phase C: within-segment prefix via match_any/ballot, sum TP contributions
    float acc = 0.0f;
    for (int s = w; s < NSEG; s += 8) {
        unsigned v = se[s * 32 + lane];
        bool valid = (v & 32u) != 0;
        int c = v & 31u;
        bool tp = (v & 64u) != 0;
        unsigned cc = valid ? (unsigned)c : 255u;
        unsigned peers = __match_any_sync(0xffffffffu, cc);
        unsigned tpb = __ballot_sync(0xffffffffu, tp);
        if (tp) {
            unsigned ltm = (1u << lane) - 1u;
            int Tw = __popc(peers & tpb & ltm);
            int Fw = __popc(peers & ltm) - Tw;
            int T = s_base[0][c] + s_tpc[s][c] + Tw;
            int F = s_base[1][c] + s_fpc[s][c] + Fw;
            float denr = (float)g_gt[c] + 1e-6f;
            bool first = (b == 0) && (s == 0) && (lane == 0);
            float p_prev = first ? 1.0f
                                 : (float)T / ((float)(T + F) + 1e-6f);
            float p_new = (float)(T + 1) / ((float)(T + 1 + F) + 1e-6f);
            acc += (1.0f / denr) * 0.5f * (p_prev + p_new);
        }
    }

    #pragma unroll
    for (int o = 16; o > 0; o >>= 1)
        acc += __shfl_xor_sync(0xffffffffu, acc, o);
    if (lane == 0) s_wsum[w] = acc;
    __syncthreads();
    if (t == 0) {
        float s = 0.0f;
        #pragma unroll
        for (int i = 0; i < 8; i++) s += s_wsum[i];
        g_ap_blk[b] = s;
    }
}

// ---------------------------------------------------------------------------
// Kernel 3: final reduction + divide; re-zero accumulators for the next replay.
// ---------------------------------------------------------------------------
__global__ __launch_bounds__(256) void k_final(float* __restrict__ out) {
    int t = threadIdx.x;
    __shared__ float sv[G];
    if (t < G) sv[t] = g_ap_blk[t];
    __syncthreads();
    #pragma unroll
    for (int o = 64; o > 0; o >>= 1) {
        if (t < o && t + o < G) sv[t] += sv[t + o];
        __syncthreads();
    }
    if (t == 0) {
        int n = 0;
        #pragma unroll
        for (int c = 0; c < NCLS; c++) n += (g_gt[c] > 0);
        out[0] = sv[0] / fmaxf((float)n, 1.0f);
    }
    __syncthreads();   // t==0 done reading g_gt
    int* tp0 = &g_tp_part[0][0];
    int* fp0 = &g_fp_part[0][0];
    for (int k = t; k < NCLS * G; k += 256) { tp0[k] = 0; fp0[k] = 0; }
    if (t < NCLS) g_gt[t] = 0;
}

extern "C" void kernel_launch(void* const* d_in, const int* in_sizes, int n_in,
                              void* d_out, int out_size) {
    const float* target = (const float*)d_in[0];
    const float* output = (const float*)d_in[1];
    float* out = (float*)d_out;

    k_per_image<<<NBLK, NTH>>>(target, output);
    k_apfinal<<<G, 256>>>();
    k_final<<<1, 256>>>(out);
}